// round 1
// baseline (speedup 1.0000x reference)
#include <cuda_runtime.h>
#include <cuda_bf16.h>
#include <math_constants.h>

// PositionEncoding: out[b,s,e] = is_class ? E_class[class_id][e]
//                                         : interleave(sin, cos)(v * 2^i * pi)
// B=64, S=8192, E=64 (32 levels), CLASS_NUM=4096.
//
// Key precision fact: fl32(v * (2^i * pi_f)) == 2^i * fl32(v * pi_f) exactly
// (power-of-two scaling commutes with fp32 rounding). So the reference angle
// for level i is exactly 2^i * a0 with a0 = fl32(v * pi_f). We reduce
// 2^i * a0 mod 2pi in double (error ~2.4e-7 rad), then use fast __sincosf.

#define NTOK   (64 * 8192)     // 524288 tokens
#define EDIM   64
#define TPT    16              // threads per token, each owns 2 levels (one float4)

__global__ __launch_bounds__(256)
void pos_enc_kernel(const float* __restrict__ values,
                    const float4* __restrict__ E_class,   // [4096][16] float4
                    const int* __restrict__ class_ids,
                    const int* __restrict__ is_class,
                    float4* __restrict__ out)             // [NTOK][16] float4
{
    unsigned gid = blockIdx.x * blockDim.x + threadIdx.x;
    unsigned tok = gid >> 4;         // token index
    unsigned t   = gid & 15u;        // which float4 within the token (levels 2t, 2t+1)
    if (tok >= NTOK) return;

    float4 o;
    if (__ldg(&is_class[tok]) == 1) {
        int cid = __ldg(&class_ids[tok]);
        o = __ldg(&E_class[(unsigned)cid * 16u + t]);
    } else {
        const float  PI_F     = 3.14159265358979323846f;
        const double INV_2PI  = 0.15915494309189534940;   // 1/(2pi)
        const double TWO_PI_D = 6.28318530717958647693;
        const float  PI_HI    = 3.14159265358979323846f;
        const float  TWO_PI_F = 6.28318530717958647693f;

        float v  = __ldg(&values[tok]);
        float a0 = v * PI_F;                         // fl32(v*pi) — matches reference
        // exact scaling: angle for level (2t) is a0 * 2^(2t)
        double x = (double)a0 * (double)(1u << (2u * t));
        double k = rint(x * INV_2PI);
        float  r0 = (float)fma(-k, TWO_PI_D, x);     // x mod 2pi in [-pi, pi]
        // level 2t+1: double the reduced angle, fold back into [-pi, pi]
        float r1 = r0 + r0;
        if (r1 >  PI_HI) r1 -= TWO_PI_F;
        if (r1 < -PI_HI) r1 += TWO_PI_F;

        __sincosf(r0, &o.x, &o.y);
        __sincosf(r1, &o.z, &o.w);
    }
    out[tok * 16u + t] = o;
}

extern "C" void kernel_launch(void* const* d_in, const int* in_sizes, int n_in,
                              void* d_out, int out_size)
{
    const float*  values    = (const float*)d_in[0];
    const float4* E_class   = (const float4*)d_in[1];
    const int*    class_ids = (const int*)d_in[2];
    const int*    is_class  = (const int*)d_in[3];
    float4*       out       = (float4*)d_out;

    const int threads = 256;
    const int total   = NTOK * TPT;                 // 8,388,608 threads
    const int blocks  = (total + threads - 1) / threads;
    pos_enc_kernel<<<blocks, threads>>>(values, E_class, class_ids, is_class, out);
}

// round 2
// speedup vs baseline: 3.0318x; 3.0318x over previous
#include <cuda_runtime.h>
#include <cuda_bf16.h>

// PositionEncoding: out[b,s,:] = is_class ? E_class[class_id] : sincos(v * 2^i * pi)
// B=64, S=8192, 32 levels (E=64), CLASS_NUM=4096.
//
// FP64-free angle reduction ("turns" arithmetic):
//   reference angle for level i is exactly 2^i * a0, a0 = fl32(v*pi_f)
//   (power-of-two scaling commutes with fp32 rounding).
//   u_i = frac(a0 * (1/2pi) * 2^i)  computed with a two-float 1/2pi:
//     s_hi + s_lo = a0*(C_HI+C_LO) to ~47 bits (exact FMA split),
//     y = s*2^i is EXACT in fp32, y - floorf(y) is EXACT,
//   so worst-case turn error ~2^-18 -> angle error ~2.4e-5 rad << 1e-3 tol.
//   theta = (u - rint(u)) * 2pi in [-pi,pi] -> fast __sincosf (MUFU).
// Odd level (i+1) derived by doubling the turn and refolding.

#define NTOK   (64 * 8192)     // 524288 tokens
#define UNROLL 4               // tokens per thread (MLP batching)

__global__ __launch_bounds__(256)
void pos_enc_kernel(const float* __restrict__ values,
                    const float4* __restrict__ E_class,   // [4096][16] float4
                    const int* __restrict__ class_ids,
                    const int* __restrict__ is_class,
                    float4* __restrict__ out)             // [NTOK][16] float4
{
    unsigned gid  = blockIdx.x * blockDim.x + threadIdx.x;
    unsigned t    = gid & 15u;          // float4 slot -> levels 2t, 2t+1
    unsigned tok0 = (gid >> 4) * UNROLL;
    if (tok0 >= NTOK) return;

    // two-float 1/(2pi): C_HI + C_LO ~ 47 bits (folded at compile time)
    constexpr double INV2PI_D = 0.15915494309189533577;
    constexpr float  C_HI = (float)INV2PI_D;
    constexpr float  C_LO = (float)(INV2PI_D - (double)C_HI);
    const float PI_F     = 3.14159265358979323846f;   // rounds to pi_f32
    const float TWO_PI_F = 6.28318530717958647693f;

    // 2^(2t) as exact fp32 via exponent-bit trick
    float scale_e = __uint_as_float((127u + 2u * t) << 23);

    // ---- front-load all scalar inputs (MLP = 12) ----
    int   ic[UNROLL], cid[UNROLL];
    float v[UNROLL];
#pragma unroll
    for (int j = 0; j < UNROLL; j++) {
        ic[j]  = __ldg(&is_class[tok0 + j]);
        cid[j] = __ldg(&class_ids[tok0 + j]);
        v[j]   = __ldg(&values[tok0 + j]);
    }

    // ---- issue all predicated E_class gathers early ----
    float4 cls[UNROLL];
#pragma unroll
    for (int j = 0; j < UNROLL; j++) {
        if (ic[j] == 1)
            cls[j] = __ldg(&E_class[(unsigned)cid[j] * 16u + t]);
    }

    // ---- compute + store ----
#pragma unroll
    for (int j = 0; j < UNROLL; j++) {
        float4 o;
        if (ic[j] == 1) {
            o = cls[j];
        } else {
            float a0   = v[j] * PI_F;                 // fl32(v*pi) — matches reference
            float s_hi = a0 * C_HI;
            float perr = fmaf(a0, C_HI, -s_hi);       // exact residual of a0*C_HI
            float s_lo = fmaf(a0, C_LO, perr);        // two-float tail, ~47 bits total
            float y_hi = s_hi * scale_e;              // exact (pow2 scale)
            float y_lo = s_lo * scale_e;              // exact
            float f    = (y_hi - floorf(y_hi)) + (y_lo - floorf(y_lo)); // exact fracs
            float w0   = f - rintf(f);                // turn in [-0.5, 0.5]
            float w1   = w0 + w0;                     // level 2t+1: double & refold
            w1 -= rintf(w1);
            __sincosf(w0 * TWO_PI_F, &o.x, &o.y);
            __sincosf(w1 * TWO_PI_F, &o.z, &o.w);
        }
        out[(tok0 + j) * 16u + t] = o;
    }
}

extern "C" void kernel_launch(void* const* d_in, const int* in_sizes, int n_in,
                              void* d_out, int out_size)
{
    const float*  values    = (const float*)d_in[0];
    const float4* E_class   = (const float4*)d_in[1];
    const int*    class_ids = (const int*)d_in[2];
    const int*    is_class  = (const int*)d_in[3];
    float4*       out       = (float4*)d_out;

    const int threads = 256;
    const long long total = (long long)(NTOK / UNROLL) * 16;   // 2,097,152 threads
    const int blocks  = (int)((total + threads - 1) / threads);
    pos_enc_kernel<<<blocks, threads>>>(values, E_class, class_ids, is_class, out);
}

// round 3
// speedup vs baseline: 3.8414x; 1.2670x over previous
#include <cuda_runtime.h>
#include <cuda_bf16.h>

// PositionEncoding: out[b,s,:] = is_class ? E_class[class_id] : sincos(v * 2^i * pi)
// B=64, S=8192, 32 levels (E=64), CLASS_NUM=4096.
//
// FP64-free angle reduction in "turns" (see R1 comment): exact pow2 scaling +
// two-float 1/2pi split keeps angle error ~2.4e-5 rad << 1e-3 tol; __sincosf
// on the reduced argument (MUFU fast path).
//
// R2 change: scalar per-token inputs for the 4-token unroll are contiguous and
// 16B aligned -> load as float4/int4/int4 (3 LDG.128 instead of 12 LDG.32),
// and stream output stores with __stcs (written once, never re-read).

#define NTOK   (64 * 8192)     // 524288 tokens
#define UNROLL 4               // tokens per thread (one vector load each)

__global__ __launch_bounds__(256)
void pos_enc_kernel(const float4* __restrict__ values4,    // [NTOK/4]
                    const float4* __restrict__ E_class,    // [4096][16] float4
                    const int4*  __restrict__ class_ids4,  // [NTOK/4]
                    const int4*  __restrict__ is_class4,   // [NTOK/4]
                    float4* __restrict__ out)               // [NTOK][16] float4
{
    unsigned gid  = blockIdx.x * blockDim.x + threadIdx.x;
    unsigned t    = gid & 15u;          // float4 slot -> levels 2t, 2t+1
    unsigned grp  = gid >> 4;           // token group (4 tokens)
    unsigned tok0 = grp * UNROLL;
    if (tok0 >= NTOK) return;

    // two-float 1/(2pi): C_HI + C_LO ~ 47 bits (folded at compile time)
    constexpr double INV2PI_D = 0.15915494309189533577;
    constexpr float  C_HI = (float)INV2PI_D;
    constexpr float  C_LO = (float)(INV2PI_D - (double)C_HI);
    const float PI_F     = 3.14159265358979323846f;   // rounds to pi_f32
    const float TWO_PI_F = 6.28318530717958647693f;

    // 2^(2t) as exact fp32 via exponent-bit trick
    float scale_e = __uint_as_float((127u + 2u * t) << 23);

    // ---- 3 vector loads cover all 12 per-token scalars (MLP = 3) ----
    float4 v4 = __ldg(&values4[grp]);
    int4   c4 = __ldg(&class_ids4[grp]);
    int4   m4 = __ldg(&is_class4[grp]);

    float v[UNROLL]  = { v4.x, v4.y, v4.z, v4.w };
    int   cid[UNROLL]= { c4.x, c4.y, c4.z, c4.w };
    int   ic[UNROLL] = { m4.x, m4.y, m4.z, m4.w };

    // ---- issue all predicated E_class gathers early (overlap latency) ----
    float4 cls[UNROLL];
#pragma unroll
    for (int j = 0; j < UNROLL; j++) {
        if (ic[j] == 1)
            cls[j] = __ldg(&E_class[(unsigned)cid[j] * 16u + t]);
    }

    // ---- compute + streaming store ----
#pragma unroll
    for (int j = 0; j < UNROLL; j++) {
        float4 o;
        if (ic[j] == 1) {
            o = cls[j];
        } else {
            float a0   = v[j] * PI_F;                 // fl32(v*pi) — matches reference
            float s_hi = a0 * C_HI;
            float perr = fmaf(a0, C_HI, -s_hi);       // exact residual of a0*C_HI
            float s_lo = fmaf(a0, C_LO, perr);        // two-float tail, ~47 bits total
            float y_hi = s_hi * scale_e;              // exact (pow2 scale)
            float y_lo = s_lo * scale_e;              // exact
            float f    = (y_hi - floorf(y_hi)) + (y_lo - floorf(y_lo)); // exact fracs
            float w0   = f - rintf(f);                // turn in [-0.5, 0.5]
            float w1   = w0 + w0;                     // level 2t+1: double & refold
            w1 -= rintf(w1);
            __sincosf(w0 * TWO_PI_F, &o.x, &o.y);
            __sincosf(w1 * TWO_PI_F, &o.z, &o.w);
        }
        __stcs(&out[(tok0 + j) * 16u + t], o);        // evict-first: never re-read
    }
}

extern "C" void kernel_launch(void* const* d_in, const int* in_sizes, int n_in,
                              void* d_out, int out_size)
{
    const float4* values4    = (const float4*)d_in[0];
    const float4* E_class    = (const float4*)d_in[1];
    const int4*   class_ids4 = (const int4*)d_in[2];
    const int4*   is_class4  = (const int4*)d_in[3];
    float4*       out        = (float4*)d_out;

    const int threads = 256;
    const long long total = (long long)(NTOK / UNROLL) * 16;   // 2,097,152 threads
    const int blocks  = (int)((total + threads - 1) / threads);
    pos_enc_kernel<<<blocks, threads>>>(values4, E_class, class_ids4, is_class4, out);
}